// round 13
// baseline (speedup 1.0000x reference)
#include <cuda_runtime.h>

#define NV 23
#define NN 529            // 23*23
#define TV 12
#define ROWLEN 6348       // N*N*T floats per batch row
#define MSTRIDE (NV*TV)   // 276 floats between consecutive m at fixed i
#define NTHREADS 736      // 23 warps; warp w <-> i = w
#define NBLOCKS 148       // 1 CTA per SM
#define WIN 32            // batches per window (= lane count)

__global__ __launch_bounds__(NTHREADS, 1)
void gat_kernel(const float* __restrict__ flow,
                const int*   __restrict__ adj,
                const float* __restrict__ W,
                float*       __restrict__ out,
                int B)
{
    // att_s[(i*23 + m)*23 + k] = normalized attention  (47.5 KB, < 48 KB static)
    __shared__ float att_s[NV * NV * NV];

    const int tid  = threadIdx.x;
    const int lane = tid & 31;
    const int warp = tid >> 5;          // = i owned by this warp

    // ---- build attention into shared: thread t<529 <-> (i=t/23, k=t%23) ----
    if (tid < NN) {
        const int ii = tid / NV;
        const int k  = tid - ii * NV;
        const float* wr = W + tid * NV;
        const int*   ar = adj + k * NV;

        float a[NV];
        float mn = 0.0f;                          // = min(min_m W, 0)
        #pragma unroll
        for (int m = 0; m < NV; ++m) {
            a[m] = wr[m];
            mn = fminf(mn, a[m]);
        }
        float s = 0.0f;
        #pragma unroll
        for (int m = 0; m < NV; ++m) {
            const int ad = (k == m) ? 1 : __ldg(ar + m);   // forced self-loop
            const float v = (ad != 0) ? (a[m] - mn) : 0.0f;
            a[m] = v;
            s += v;
        }
        const float inv = 1.0f / s;
        #pragma unroll
        for (int m = 0; m < NV; ++m)
            att_s[(ii * NV + m) * NV + k] = a[m] * inv;    // [i][m][k] layout
    }
    __syncthreads();                     // the ONLY block barrier

    // ---- barrier-free main loop: lane = batch, warp = i ----
    const float* ai   = att_s + warp * (NV * NV);
    const float* gp0  = flow + warp * TV + (TV - 1);
    const int    step = WIN * gridDim.x;

    for (int b0 = blockIdx.x * WIN; b0 < B; b0 += step) {
        const int  b     = b0 + lane;
        const bool valid = (b < B);

        // 23 independent scattered loads: d[m] = flow[b, m, i, T-1]
        const float* gp = gp0 + (size_t)(valid ? b : 0) * ROWLEN;
        float d[NV];
        #pragma unroll
        for (int m = 0; m < NV; ++m)
            d[m] = __ldg(gp + m * MSTRIDE);

        // acc[k] = sum_m att[i,k,m] * d[m]   (att via warp-uniform broadcast LDS)
        float acc[NV];
        #pragma unroll
        for (int k = 0; k < NV; ++k) acc[k] = 0.0f;
        #pragma unroll
        for (int m = 0; m < NV; ++m) {
            const float  dm = d[m];
            const float* am = ai + m * NV;
            #pragma unroll
            for (int k = 0; k < NV; ++k)
                acc[k] = fmaf(am[k], dm, acc[k]);
        }

        // write x[b, i, 0..22] : 92 contiguous bytes per thread
        if (valid) {
            float* op = out + (size_t)b * NN + warp * NV;
            #pragma unroll
            for (int k = 0; k < NV; ++k)
                op[k] = acc[k];
        }
    }
}

extern "C" void kernel_launch(void* const* d_in, const int* in_sizes, int n_in,
                              void* d_out, int out_size) {
    const float* flow = (const float*)d_in[0];   // (B, N, N, T) fp32
    const int*   adj  = (const int*)  d_in[1];   // (N, N) int32
    const float* W    = (const float*)d_in[2];   // (N, N, N) fp32
    float*       out  = (float*)d_out;           // (B, N, N, 1) fp32

    const int B = in_sizes[0] / ROWLEN;
    gat_kernel<<<NBLOCKS, NTHREADS>>>(flow, adj, W, out, B);
}

// round 14
// speedup vs baseline: 1.6561x; 1.6561x over previous
#include <cuda_runtime.h>
#include <cstdint>

#define NV 23
#define NN 529          // 23*23
#define TV 12
#define ROWLEN 6348     // N*N*T floats per batch
#define NTHREADS 544    // 17 warps; threads 529..543 idle but sync
#define NBLOCKS 296     // 148 SMs * 2 blocks
#define CHUNK 4         // batches per barrier

__global__ __launch_bounds__(NTHREADS, 2)
void gat_kernel(const float* __restrict__ flow,
                const int*   __restrict__ adj,
                const float* __restrict__ W,
                float*       __restrict__ out,
                int B)
{
    __shared__ float dbuf[2][CHUNK][NN];  // staged slices d[m*23+i]
    __shared__ int   adj_s[NN];

    const int tid = threadIdx.x;
    const bool act = (tid < NN);
    int i_idx = 0, k_idx = 0;
    if (act) { i_idx = tid / NV; k_idx = tid - i_idx * NV; }

    // ---- adjacency with forced self-loops ----
    if (act) {
        int a = adj[tid];
        if (i_idx == k_idx) a = 1;
        adj_s[tid] = a;
    }
    __syncthreads();

    // ---- per-thread attention row att[i_idx][k_idx][0..22] in registers ----
    float att[NV];
    if (act) {
        const float* wr = W + tid * NV;
        float mn = 0.0f;                       // = min(min_m W, 0)
        #pragma unroll
        for (int m = 0; m < NV; ++m) {
            att[m] = wr[m];
            mn = fminf(mn, att[m]);
        }
        float s = 0.0f;
        #pragma unroll
        for (int m = 0; m < NV; ++m) {
            float a = (adj_s[k_idx * NV + m] != 0) ? (att[m] - mn) : 0.0f;
            att[m] = a;
            s += a;
        }
        float inv = 1.0f / s;
        #pragma unroll
        for (int m = 0; m < NV; ++m) att[m] *= inv;
    }

    // ---- chunked grid-stride batch loop, double-buffered, 1 barrier / 4 batches ----
    const int step = gridDim.x * CHUNK;
    int base = blockIdx.x * CHUNK;
    const float* gsrc = flow + tid * TV + (TV - 1);   // this thread's gather point

    // prologue: stage chunk at 'base'; prefetch chunk at base+step into L2
    if (act) {
        #pragma unroll
        for (int c = 0; c < CHUNK; ++c) {
            const int b = base + c;
            float v = (b < B) ? __ldcs(gsrc + (size_t)b * ROWLEN) : 0.0f;
            dbuf[0][c][tid] = v;
        }
        #pragma unroll
        for (int c = 0; c < CHUNK; ++c) {
            int b = base + step + c; if (b >= B) b = B - 1;
            const float* pa = gsrc + (size_t)b * ROWLEN;
            asm volatile("prefetch.global.L2 [%0];" :: "l"(pa));
        }
    }
    __syncthreads();

    int p = 0;
    for (; base < B; base += step) {
        const int nbase = base + step;

        // 1) real loads for next chunk (should largely hit L2 via prefetch)
        float nv[CHUNK];
        if (act) {
            #pragma unroll
            for (int c = 0; c < CHUNK; ++c) {
                const int b = nbase + c;
                nv[c] = (b < B) ? __ldcs(gsrc + (size_t)b * ROWLEN) : 0.0f;
            }
            // 2) fire-and-forget L2 prefetch two chunks ahead — keeps DRAM
            //    issuing during the compute/STS/barrier phase below
            #pragma unroll
            for (int c = 0; c < CHUNK; ++c) {
                int b = base + 2 * step + c; if (b >= B) b = B - 1;
                const float* pa = gsrc + (size_t)b * ROWLEN;
                asm volatile("prefetch.global.L2 [%0];" :: "l"(pa));
            }
        }

        // 3) compute CHUNK outputs from staged buffers (overlaps load latency)
        if (act) {
            #pragma unroll
            for (int c = 0; c < CHUNK; ++c) {
                const int b = base + c;
                if (b < B) {
                    const float* d = dbuf[p][c];
                    float acc = 0.0f;
                    #pragma unroll
                    for (int m = 0; m < NV; ++m)
                        acc = fmaf(att[m], d[m * NV + i_idx], acc);
                    __stcs(out + (size_t)b * NN + tid, acc);   // coalesced, evict-first
                }
            }
        }

        // 4) land prefetched chunk into the other buffer
        if (act) {
            #pragma unroll
            for (int c = 0; c < CHUNK; ++c)
                dbuf[p ^ 1][c][tid] = nv[c];
        }
        __syncthreads();
        p ^= 1;
    }
}

extern "C" void kernel_launch(void* const* d_in, const int* in_sizes, int n_in,
                              void* d_out, int out_size) {
    const float* flow = (const float*)d_in[0];   // (B, N, N, T) fp32
    const int*   adj  = (const int*)  d_in[1];   // (N, N) int32
    const float* W    = (const float*)d_in[2];   // (N, N, N) fp32
    float*       out  = (float*)d_out;           // (B, N, N, 1) fp32

    const int B = in_sizes[0] / ROWLEN;
    gat_kernel<<<NBLOCKS, NTHREADS>>>(flow, adj, W, out, B);
}

// round 15
// speedup vs baseline: 1.8506x; 1.1175x over previous
#include <cuda_runtime.h>
#include <cstdint>

#define NV 23
#define NN 529          // 23*23
#define TV 12
#define ROWLEN 6348     // N*N*T floats per batch
#define NTHREADS 544    // 17 warps; threads 529..543 idle but sync
#define NBLOCKS 296     // 148 SMs * 2 blocks
#define CHUNK 4         // batches per barrier/ticket

__device__ unsigned int g_ticket;

__global__ void reset_ticket() { g_ticket = NBLOCKS; }

__global__ __launch_bounds__(NTHREADS, 2)
void gat_kernel(const float* __restrict__ flow,
                const int*   __restrict__ adj,
                const float* __restrict__ W,
                float*       __restrict__ out,
                int B)
{
    __shared__ float dbuf[2][CHUNK][NN];  // staged slices d[m*23+i]
    __shared__ int   adj_s[NN];
    __shared__ int   sticket[2];          // next chunk id, double-slotted by parity

    const int tid = threadIdx.x;
    const bool act = (tid < NN);
    int i_idx = 0, k_idx = 0;
    if (act) { i_idx = tid / NV; k_idx = tid - i_idx * NV; }

    const int nchunks = (B + CHUNK - 1) / CHUNK;      // 4096

    // ---- adjacency with forced self-loops; grab first dynamic ticket ----
    if (act) {
        int a = adj[tid];
        if (i_idx == k_idx) a = 1;
        adj_s[tid] = a;
    }
    if (tid == 0)
        sticket[1] = (int)atomicAdd(&g_ticket, 1u);   // read at top of iter 0 (p=0 reads slot 1? see below)
    __syncthreads();

    // ---- per-thread attention row att[i_idx][k_idx][0..22] in registers ----
    float att[NV];
    if (act) {
        const float* wr = W + tid * NV;
        float mn = 0.0f;                       // = min(min_m W, 0)
        #pragma unroll
        for (int m = 0; m < NV; ++m) {
            att[m] = wr[m];
            mn = fminf(mn, att[m]);
        }
        float s = 0.0f;
        #pragma unroll
        for (int m = 0; m < NV; ++m) {
            float a = (adj_s[k_idx * NV + m] != 0) ? (att[m] - mn) : 0.0f;
            att[m] = a;
            s += a;
        }
        float inv = 1.0f / s;
        #pragma unroll
        for (int m = 0; m < NV; ++m) att[m] *= inv;
    }

    const float* gsrc = flow + tid * TV + (TV - 1);   // this thread's gather point

    // ---- prologue: stage pre-assigned chunk (= blockIdx.x) ----
    int cur = blockIdx.x;
    if (act) {
        #pragma unroll
        for (int c = 0; c < CHUNK; ++c) {
            const int b = cur * CHUNK + c;
            dbuf[0][c][tid] = (b < B) ? __ldcs(gsrc + (size_t)b * ROWLEN) : 0.0f;
        }
    }
    __syncthreads();

    // ---- ticket-scheduled loop: loads at top, ticket grabbed under barrier ----
    int p = 0;
    while (cur < nchunks) {
        const int nxt = sticket[p ^ 1];               // grabbed last iteration

        // 1) issue loads for next chunk FIRST (enters DRAM queue at period start)
        float nv[CHUNK];
        if (act) {
            #pragma unroll
            for (int c = 0; c < CHUNK; ++c) {
                const int b = nxt * CHUNK + c;
                nv[c] = (b < B && nxt < nchunks)
                      ? __ldcs(gsrc + (size_t)b * ROWLEN) : 0.0f;
            }
        }

        // 2) grab ticket for the iteration after next (latency hides under
        //    compute + barrier; written to the slot readers aren't using)
        if (tid == 0)
            sticket[p] = (int)atomicAdd(&g_ticket, 1u);

        // 3) compute CHUNK outputs from staged buffers
        if (act) {
            #pragma unroll
            for (int c = 0; c < CHUNK; ++c) {
                const int b = cur * CHUNK + c;
                if (b < B) {
                    const float* d = dbuf[p][c];
                    float acc = 0.0f;
                    #pragma unroll
                    for (int m = 0; m < NV; ++m)
                        acc = fmaf(att[m], d[m * NV + i_idx], acc);
                    __stcs(out + (size_t)b * NN + tid, acc);   // coalesced
                }
            }
        }

        // 4) land prefetched chunk into the other buffer
        if (act) {
            #pragma unroll
            for (int c = 0; c < CHUNK; ++c)
                dbuf[p ^ 1][c][tid] = nv[c];
        }
        __syncthreads();
        cur = nxt;
        p ^= 1;
    }
}

extern "C" void kernel_launch(void* const* d_in, const int* in_sizes, int n_in,
                              void* d_out, int out_size) {
    const float* flow = (const float*)d_in[0];   // (B, N, N, T) fp32
    const int*   adj  = (const int*)  d_in[1];   // (N, N) int32
    const float* W    = (const float*)d_in[2];   // (N, N, N) fp32
    float*       out  = (float*)d_out;           // (B, N, N, 1) fp32

    const int B = in_sizes[0] / ROWLEN;
    reset_ticket<<<1, 1>>>();
    gat_kernel<<<NBLOCKS, NTHREADS>>>(flow, adj, W, out, B);
}